// round 4
// baseline (speedup 1.0000x reference)
#include <cuda_runtime.h>

#define BS           24
#define C_REP        16
#define H_DIM        320
#define W_DIM        320
#define HW           (H_DIM * W_DIM)         // 102400
#define HW4          (HW / 4)                // 25600
#define N_PIX        (BS * HW)               // 2457600
#define N_VEC        (N_PIX / 4)             // 614400
#define NUM_CLASSES  4
#define NUM_MICRO    4
#define NSEG         (NUM_CLASSES * NUM_MICRO)
#define SEG_STRIDE   17
#define SCRATCH_N    (NSEG * SEG_STRIDE)     // 272
#define MOMENTUM     0.99f

#define BLOCK_DIM    256
#define GRID_DIM     (N_VEC / BLOCK_DIM)     // 2400, exact cover, 1 vec4/thread

__device__ float g_scratch[SCRATCH_N];   // zero-init at load; reset each call
__device__ unsigned int g_ticket;        // zero-init; reset each call

__global__ __launch_bounds__(BLOCK_DIM) void fused_kernel(
    const float* __restrict__ rep,          // [BS, C_REP, H, W]
    const int* __restrict__ pmi,            // [BS, H, W, NUM_CLASSES]
    const int* __restrict__ target,         // [BS, H, W]
    const int* __restrict__ smask,          // [H, W]
    const unsigned char* __restrict__ cond, // [BS, H, W] bool
    const float* __restrict__ protos,       // [NSEG*C_REP]
    float* __restrict__ out                 // [NSEG*C_REP]
) {
    __shared__ float s_acc[SCRATCH_N];
    const int tid = threadIdx.x;
    for (int i = tid; i < SCRATCH_N; i += BLOCK_DIM)
        s_acc[i] = 0.0f;
    __syncthreads();

    const unsigned v = blockIdx.x * BLOCK_DIM + tid;   // one vec4 per thread
    const unsigned n0  = 4u * v;
    const unsigned b   = n0 / HW;
    const unsigned hw4 = n0 % HW;                      // multiple of 4

    // ---- all independent loads, issued together (no dead latency window) ----
    int4   t4 = ((const int4*)target)[v];
    uchar4 c4 = ((const uchar4*)cond)[v];
    int4   m4 = ((const int4*)smask)[hw4 >> 2];

    const float4* __restrict__ r4 =
        (const float4*)(rep + (size_t)b * (C_REP * HW)) + (hw4 >> 2);

    float4 va[8];                      // channels 0..7 (unconditional)
    #pragma unroll
    for (int c = 0; c < 8; c++)
        va[c] = r4[(size_t)c * HW4];

    float4 vb[8];                      // channels 8..15 (unconditional)
    #pragma unroll
    for (int c = 0; c < 8; c++)
        vb[c] = r4[(size_t)(c + 8) * HW4];

    // ---- predicates (arrive with the first rep bytes) ----
    int tgt[4] = {t4.x, t4.y, t4.z, t4.w};
    bool val[4];
    val[0] = (t4.x != 0) & (c4.x != 0) & (m4.x == 1);
    val[1] = (t4.y != 0) & (c4.y != 0) & (m4.y == 1);
    val[2] = (t4.z != 0) & (c4.z != 0) & (m4.z == 1);
    val[3] = (t4.w != 0) & (c4.w != 0) & (m4.w == 1);

    if (val[0] | val[1] | val[2] | val[3]) {
        int seg[4];
        #pragma unroll
        for (int k = 0; k < 4; k++)
            if (val[k])
                seg[k] = tgt[k] * NUM_MICRO
                       + pmi[4u * (n0 + k) + (unsigned)tgt[k]];

        #pragma unroll
        for (int k = 0; k < 4; k++) {
            if (val[k]) {
                float* base = &s_acc[seg[k] * SEG_STRIDE];
                #pragma unroll
                for (int c = 0; c < 8; c++) {
                    const float* f = (const float*)&va[c];
                    atomicAdd(&base[c], f[k]);
                }
                #pragma unroll
                for (int c = 0; c < 8; c++) {
                    const float* f = (const float*)&vb[c];
                    atomicAdd(&base[c + 8], f[k]);
                }
                atomicAdd(&base[C_REP], 1.0f);
            }
        }
    }
    __syncthreads();

    // ---- flush per-CTA partials (REDG: no return value used) ----
    for (int i = tid; i < SCRATCH_N; i += BLOCK_DIM) {
        float valf = s_acc[i];
        if (valf != 0.0f) atomicAdd(&g_scratch[i], valf);
    }

    // ---- last CTA: finalize + reset state for next graph replay ----
    __shared__ bool s_last;
    __threadfence();
    if (tid == 0) {
        unsigned t = atomicAdd(&g_ticket, 1u);
        s_last = (t == GRID_DIM - 1);
    }
    __syncthreads();
    if (!s_last) return;

    if (tid < NSEG * C_REP) {
        int sg = tid >> 4;
        int c = tid & 15;
        float cnt = __ldcg(&g_scratch[sg * SEG_STRIDE + C_REP]);
        float sum = __ldcg(&g_scratch[sg * SEG_STRIDE + c]);
        float mean = sum / fmaxf(cnt, 1.0f);
        float p = protos[tid];
        out[tid] = (cnt > 0.0f) ? (MOMENTUM * p + (1.0f - MOMENTUM) * mean) : p;
    }
    __syncthreads();

    for (int i = tid; i < SCRATCH_N; i += BLOCK_DIM)
        g_scratch[i] = 0.0f;
    if (tid == 0) g_ticket = 0u;
}

extern "C" void kernel_launch(void* const* d_in, const int* in_sizes, int n_in,
                              void* d_out, int out_size) {
    const float* rep           = (const float*)d_in[0];
    const int* pmi             = (const int*)d_in[1];
    const int* target          = (const int*)d_in[2];
    const int* smask           = (const int*)d_in[3];
    const unsigned char* cond  = (const unsigned char*)d_in[4];
    const float* protos        = (const float*)d_in[5];
    float* out                 = (float*)d_out;

    fused_kernel<<<GRID_DIM, BLOCK_DIM>>>(rep, pmi, target, smask, cond,
                                          protos, out);
}

// round 5
// speedup vs baseline: 1.1352x; 1.1352x over previous
#include <cuda_runtime.h>

#define BS           24
#define C_REP        16
#define H_DIM        320
#define W_DIM        320
#define HW           (H_DIM * W_DIM)         // 102400
#define N_PIX        (BS * HW)               // 2457600
#define NUM_CLASSES  4
#define NUM_MICRO    4
#define NSEG         (NUM_CLASSES * NUM_MICRO)
#define SEG_STRIDE   17
#define SCRATCH_N    (NSEG * SEG_STRIDE)     // 272
#define MOMENTUM     0.99f

#define BLOCK_DIM    256
#define PIX_PER_CTA  4096                    // 16 pixels / thread, 4 vec4 chunks
#define VEC_PER_CTA  (PIX_PER_CTA / 4)       // 1024
#define CHUNKS       4                       // VEC_PER_CTA / BLOCK_DIM
#define GRID_DIM     (N_PIX / PIX_PER_CTA)   // 600 (4096 divides HW=102400)

__device__ float g_scratch[SCRATCH_N];   // zero-init at load; reset each call
__device__ unsigned int g_ticket;        // zero-init; reset each call

__global__ __launch_bounds__(BLOCK_DIM) void fused_kernel(
    const float* __restrict__ rep,          // [BS, C_REP, H, W]
    const int* __restrict__ pmi,            // [BS, H, W, NUM_CLASSES]
    const int* __restrict__ target,         // [BS, H, W]
    const int* __restrict__ smask,          // [H, W]
    const unsigned char* __restrict__ cond, // [BS, H, W] bool
    const float* __restrict__ protos,       // [NSEG*C_REP]
    float* __restrict__ out                 // [NSEG*C_REP]
) {
    __shared__ float s_acc[SCRATCH_N];
    __shared__ unsigned s_list[PIX_PER_CTA];   // packed (n<<2)|tgt
    __shared__ unsigned s_count;

    const int tid  = threadIdx.x;
    const int lane = tid & 31;
    for (int i = tid; i < SCRATCH_N; i += BLOCK_DIM)
        s_acc[i] = 0.0f;
    if (tid == 0) s_count = 0u;
    __syncthreads();

    // ================= Phase A: predicate stream + compaction =============
    {
        int4   t4[CHUNKS];
        uchar4 c4[CHUNKS];
        int4   m4[CHUNKS];
        const unsigned vbase = blockIdx.x * VEC_PER_CTA + tid;
        #pragma unroll
        for (int j = 0; j < CHUNKS; j++) {
            unsigned v = vbase + j * BLOCK_DIM;
            t4[j] = ((const int4*)target)[v];
            c4[j] = ((const uchar4*)cond)[v];
            m4[j] = ((const int4*)smask)[(4u * v) % HW >> 2];
        }

        #pragma unroll
        for (int j = 0; j < CHUNKS; j++) {
            unsigned n0 = 4u * (vbase + j * BLOCK_DIM);
            int tgt[4] = {t4[j].x, t4[j].y, t4[j].z, t4[j].w};
            bool val[4];
            val[0] = (t4[j].x != 0) & (c4[j].x != 0) & (m4[j].x == 1);
            val[1] = (t4[j].y != 0) & (c4[j].y != 0) & (m4[j].y == 1);
            val[2] = (t4[j].z != 0) & (c4[j].z != 0) & (m4[j].z == 1);
            val[3] = (t4[j].w != 0) & (c4[j].w != 0) & (m4[j].w == 1);

            #pragma unroll
            for (int k = 0; k < 4; k++) {
                unsigned bal = __ballot_sync(0xffffffffu, val[k]);
                if (bal) {
                    int leader = __ffs(bal) - 1;
                    unsigned base = 0;
                    if (lane == leader)
                        base = atomicAdd(&s_count, (unsigned)__popc(bal));
                    base = __shfl_sync(0xffffffffu, base, leader);
                    if (val[k]) {
                        unsigned pos = base + __popc(bal & ((1u << lane) - 1u));
                        s_list[pos] = ((n0 + k) << 2) | (unsigned)tgt[k];
                    }
                }
            }
        }
    }
    __syncthreads();

    // ================= Phase B: dense gather + accumulate ==================
    {
        const unsigned total = s_count;
        const unsigned b_cta = (blockIdx.x * PIX_PER_CTA) / HW; // CTA in 1 batch
        const float* __restrict__ rb = rep + (size_t)b_cta * (C_REP * HW)
                                           - (size_t)b_cta * HW; // rb + n = rep(b,0,hw)
        for (unsigned i = tid; i < total; i += BLOCK_DIM) {
            unsigned e = s_list[i];
            unsigned n = e >> 2;
            int tgt = (int)(e & 3u);

            // independent loads: pmi + 16 rep channels, all issued together
            int pidx = pmi[4u * n + (unsigned)tgt];
            float vv[C_REP];
            #pragma unroll
            for (int c = 0; c < C_REP; c++)
                vv[c] = rb[(size_t)c * HW + n];

            int seg = tgt * NUM_MICRO + pidx;
            float* base = &s_acc[seg * SEG_STRIDE];
            #pragma unroll
            for (int c = 0; c < C_REP; c++)
                atomicAdd(&base[c], vv[c]);
            atomicAdd(&base[C_REP], 1.0f);
        }
    }
    __syncthreads();

    // ================= flush per-CTA partials =============================
    for (int i = tid; i < SCRATCH_N; i += BLOCK_DIM) {
        float valf = s_acc[i];
        if (valf != 0.0f) atomicAdd(&g_scratch[i], valf);
    }

    // ================= last CTA: finalize + reset =========================
    __shared__ bool s_last;
    __threadfence();
    if (tid == 0) {
        unsigned t = atomicAdd(&g_ticket, 1u);
        s_last = (t == GRID_DIM - 1);
    }
    __syncthreads();
    if (!s_last) return;

    if (tid < NSEG * C_REP) {
        int sg = tid >> 4;
        int c = tid & 15;
        float cnt = __ldcg(&g_scratch[sg * SEG_STRIDE + C_REP]);
        float sum = __ldcg(&g_scratch[sg * SEG_STRIDE + c]);
        float mean = sum / fmaxf(cnt, 1.0f);
        float p = protos[tid];
        out[tid] = (cnt > 0.0f) ? (MOMENTUM * p + (1.0f - MOMENTUM) * mean) : p;
    }
    __syncthreads();

    for (int i = tid; i < SCRATCH_N; i += BLOCK_DIM)
        g_scratch[i] = 0.0f;
    if (tid == 0) g_ticket = 0u;
}

extern "C" void kernel_launch(void* const* d_in, const int* in_sizes, int n_in,
                              void* d_out, int out_size) {
    const float* rep           = (const float*)d_in[0];
    const int* pmi             = (const int*)d_in[1];
    const int* target          = (const int*)d_in[2];
    const int* smask           = (const int*)d_in[3];
    const unsigned char* cond  = (const unsigned char*)d_in[4];
    const float* protos        = (const float*)d_in[5];
    float* out                 = (float*)d_out;

    fused_kernel<<<GRID_DIM, BLOCK_DIM>>>(rep, pmi, target, smask, cond,
                                          protos, out);
}